// round 12
// baseline (speedup 1.0000x reference)
#include <cuda_runtime.h>
#include <math.h>

#define NB 4096
#define NC 1000
#define ND 2048
#define NBLK 1024
#define NMIR 32

#define TAU   6.0f
#define ALPHA 1.0f
#define BETA  5.0f
#define LR    0.1f
#define PI_F  3.14159265358979f
#define EPS_F 1e-8f
#define DECAY 0.999f   /* 1 - LR*WD */

// ---- scratch state (device globals: no allocation allowed) ----
__device__ float2 g_mv[NB * NC];     // only used by fallback variant
__device__ float  g_ptrg[NB];        // constant per row

struct KeySlot { unsigned long long k; unsigned long long pad[15]; }; // 128B
__device__ KeySlot g_key[104];
struct CntSlot { int c; int pad[31]; };                               // 128B
__device__ CntSlot g_cnt[104];
__device__ KeySlot g_mirror[104 * NMIR];   // broadcast mirrors (poll targets)

// key = [pmax_bits:32 | (4095-row):12]  (pmax>0 -> key >= 2^24, nonzero;
// float bit order == value order for positives; row packed for first-on-tie)
__device__ __forceinline__ unsigned long long make_key(float pm, int row)
{
    return (((unsigned long long)__float_as_uint(pm)) << 24)
         | (((unsigned long long)(4095 - row)) << 12);
}

__device__ __forceinline__ int atom_add1_acqrel(int* p)
{
    int v;
    asm volatile("atom.acq_rel.gpu.global.add.s32 %0, [%1], 1;"
                 : "=r"(v) : "l"(p) : "memory");
    return v;
}
__device__ __forceinline__ unsigned long long ld_acquire64(const unsigned long long* p)
{
    unsigned long long v;
    asm volatile("ld.acquire.gpu.global.u64 %0, [%1];" : "=l"(v) : "l"(p) : "memory");
    return v;
}
__device__ __forceinline__ void st_release64(unsigned long long* p, unsigned long long v)
{
    asm volatile("st.release.gpu.global.u64 [%0], %1;" :: "l"(p), "l"(v) : "memory");
}

// =====================================================================
// setup: zero key/counter/mirror slots (rerun every graph replay)
// =====================================================================
__global__ void setup_kernel()
{
    int t = blockIdx.x * blockDim.x + threadIdx.x;
    for (int s = t; s < 104 * NMIR; s += gridDim.x * blockDim.x)
        g_mirror[s].k = 0ull;
    if (t < 104) { g_key[t].k = 0ull; g_cnt[t].c = 0; }
}

// one dummy launch steers ncu's fixed capture slot (#4) onto persist_steps
__global__ void dummy_kernel() {}

// =====================================================================
// flat arrival (proven) + fanout broadcast. The completing arriver
// copies the final key into 32 mirror lines; blocks poll their mirror.
// =====================================================================
__device__ __forceinline__ void arrive_key(int t, unsigned long long kk)
{
    atomicMax(&g_key[t].k, kk);
    int old = atom_add1_acqrel(&g_cnt[t].c);
    if (old == NBLK - 1) {                     // last arriver: fan out
        unsigned long long fk = ld_acquire64(&g_key[t].k);
#pragma unroll
        for (int q = 0; q < NMIR; q++)
            st_release64(&g_mirror[t * NMIR + q].k, fk);
    }
}

__device__ __forceinline__ unsigned long long wait_key(int t, int mir)
{
    const unsigned long long* p = &g_mirror[t * NMIR + mir].k;
    unsigned long long fk;
    while ((fk = ld_acquire64(p)) == 0ull) __nanosleep(40);
    return fk;
}

// =====================================================================
// GEMM: z = x @ W + b. 64x64 tile, BK=16, 256 thr, 4x4/thr, double-buf.
// Measured 497us = 94% of scalar FFMA floor. DO NOT TOUCH.
// =====================================================================
__global__ __launch_bounds__(256) void sgemm_bias(
    const float* __restrict__ A, const float* __restrict__ B,
    const float* __restrict__ bias, float* __restrict__ C)
{
    __shared__ float As[2][16][64];
    __shared__ float Bs[2][16][64];

    const int tid = threadIdx.x;
    const int tx = tid & 15;
    const int ty = tid >> 4;
    const int rowBase = blockIdx.y * 64;
    const int colBase = blockIdx.x * 64;

    const int ar = tid >> 2;
    const int ak = (tid & 3) << 2;
    const int bk = tid >> 4;
    const int bc = (tid & 15) << 2;
    const int bgc = colBase + bc;

    float acc[4][4];
#pragma unroll
    for (int q = 0; q < 4; q++)
#pragma unroll
        for (int p = 0; p < 4; p++) acc[q][p] = 0.0f;

    {
        float4 av = *reinterpret_cast<const float4*>(
            &A[(size_t)(rowBase + ar) * ND + ak]);
        As[0][ak + 0][ar] = av.x; As[0][ak + 1][ar] = av.y;
        As[0][ak + 2][ar] = av.z; As[0][ak + 3][ar] = av.w;
        float4 bv = make_float4(0.f, 0.f, 0.f, 0.f);
        if (bgc < NC)
            bv = *reinterpret_cast<const float4*>(&B[(size_t)bk * NC + bgc]);
        *reinterpret_cast<float4*>(&Bs[0][bk][bc]) = bv;
    }
    __syncthreads();

    int buf = 0;
    for (int kt = 0; kt < ND / 16; kt++) {
        float4 pa, pb;
        const bool hasNext = (kt + 1 < ND / 16);
        if (hasNext) {
            int k0 = (kt + 1) * 16;
            pa = *reinterpret_cast<const float4*>(
                &A[(size_t)(rowBase + ar) * ND + k0 + ak]);
            pb = make_float4(0.f, 0.f, 0.f, 0.f);
            if (bgc < NC)
                pb = *reinterpret_cast<const float4*>(
                    &B[(size_t)(k0 + bk) * NC + bgc]);
        }

#pragma unroll
        for (int kk = 0; kk < 16; kk++) {
            float4 a4 = *reinterpret_cast<float4*>(&As[buf][kk][ty * 4]);
            float4 b4 = *reinterpret_cast<float4*>(&Bs[buf][kk][tx * 4]);
            float a[4] = {a4.x, a4.y, a4.z, a4.w};
            float bb[4] = {b4.x, b4.y, b4.z, b4.w};
#pragma unroll
            for (int q = 0; q < 4; q++)
#pragma unroll
                for (int p = 0; p < 4; p++)
                    acc[q][p] = fmaf(a[q], bb[p], acc[q][p]);
        }

        if (hasNext) {
            int nb = buf ^ 1;
            As[nb][ak + 0][ar] = pa.x; As[nb][ak + 1][ar] = pa.y;
            As[nb][ak + 2][ar] = pa.z; As[nb][ak + 3][ar] = pa.w;
            *reinterpret_cast<float4*>(&Bs[nb][bk][bc]) = pb;
            __syncthreads();
            buf = nb;
        }
    }

    const int cbase = colBase + tx * 4;
    if (cbase < NC) {
        float4 bv = *reinterpret_cast<const float4*>(&bias[cbase]);
#pragma unroll
        for (int q = 0; q < 4; q++) {
            int r = rowBase + ty * 4 + q;
            float4 o;
            o.x = acc[q][0] + bv.x; o.y = acc[q][1] + bv.y;
            o.z = acc[q][2] + bv.z; o.w = acc[q][3] + bv.w;
            *reinterpret_cast<float4*>(&C[(size_t)r * NC + cbase]) = o;
        }
    }
}

// =====================================================================
// Persistent kernel (template): init stats + 100 AdamW steps.
// Warp-per-row, u in registers. SMEMV: m,v in shared; else gmem (L2).
// 1024 blocks x 128 thr. Flat arrival + mirror-fanout barrier.
// Lazy jstar: only the star warp computes its argmax, from registers.
// =====================================================================
template<bool SMEMV>
__global__ __launch_bounds__(128, 7) void persist_steps(float* __restrict__ U)
{
    __shared__ float2 smv[4][SMEMV ? NC : 1];
    __shared__ unsigned long long sKey[4];
    __shared__ float  sRed4[4];
    __shared__ float2 sBC;

    const int tid  = threadIdx.x;
    const int lane = tid & 31;
    const int w    = tid >> 5;
    const int i    = blockIdx.x * 4 + w;
    const int mir  = blockIdx.x & (NMIR - 1);

    float*  Urow  = U + (size_t)i * NC;
    float2* mvrow = SMEMV ? &smv[w][0] : (g_mv + (size_t)i * NC);

    // ---- load row into registers ----
    float u[32];
#pragma unroll
    for (int k = 0; k < 32; k++) {
        int j = k * 32 + lane;
        u[k] = (j < NC) ? Urow[j] : -INFINITY;
    }

    // ---- init stats (identical arithmetic to prior rounds) ----
    float bv = -INFINITY; int bj = NC;
#pragma unroll
    for (int k = 0; k < 32; k++) {
        int j = k * 32 + lane;
        if (j < NC) { if (u[k] > bv) { bv = u[k]; bj = j; } }
    }
#pragma unroll
    for (int off = 16; off; off >>= 1) {
        float ov = __shfl_down_sync(0xffffffffu, bv, off);
        int   oj = __shfl_down_sync(0xffffffffu, bj, off);
        if (ov > bv || (ov == bv && oj < bj)) { bv = ov; bj = oj; }
    }
    bv = __shfl_sync(0xffffffffu, bv, 0);
    bj = __shfl_sync(0xffffffffu, bj, 0);

    float se = 0.0f;
#pragma unroll
    for (int k = 0; k < 32; k++) {
        int j = k * 32 + lane;
        if (j < NC) se += expf(u[k] - bv);
    }
#pragma unroll
    for (int off = 16; off; off >>= 1) se += __shfl_xor_sync(0xffffffffu, se, off);

    float l_org = logf(se);
    float l_atr = (floorf(l_org / TAU) + 0.5f) * TAU;
    const float ltrg = l_org - ALPHA * TAU *
                       sinf(PI_F * (1.0f - 2.0f * (l_org - l_atr) / TAU));
    float pm  = 1.0f / se;
    float lse = bv + l_org;     // lane-uniform
    float uy  = bv;             // z[i, y] = rowmax
    const int y = bj;

    if (lane == 0) {
        g_ptrg[i] = pm;
        sKey[w]   = make_key(pm, i);
    }
    __syncthreads();
    if (tid == 0) {
        unsigned long long kk = sKey[0];
#pragma unroll
        for (int q = 1; q < 4; q++) if (sKey[q] > kk) kk = sKey[q];
        arrive_key(1, kk);
    }

    // bias-correction running products (tid 0 only; bitwise-proven)
    double p1 = 1.0, p2 = 1.0;
    __shared__ unsigned long long sKeyFinal;

    // =================== step loop ===================
    for (int t = 1; t <= 100; t++) {
        if (tid == 0) {
            sKeyFinal = wait_key(t, mir);
            p1 *= 0.9; p2 *= 0.999;
            sBC = make_float2((float)(1.0 / (1.0 - p1)),
                              (float)(1.0 / (1.0 - p2)));
        }
        __syncthreads();

        const unsigned long long key = sKeyFinal;
        const float M     = __uint_as_float((unsigned int)(key >> 24));
        const int   istar = 4095 - (int)((key >> 12) & 0xFFF);
        const float bc1 = sBC.x, bc2 = sBC.y;

        // --- S only needed by the star row's block (ptrg L1-resident) ---
        const bool starBlk = ((istar >> 2) == (int)blockIdx.x);
        float S = 0.0f;
        if (starBlk) {
            float ps = 0.0f;
            for (int r = tid; r < NB; r += 128) {
                float d = M - g_ptrg[r];
                ps += (d > 0.0f) ? 1.0f : ((d < 0.0f) ? -1.0f : 0.0f);
            }
#pragma unroll
            for (int off = 16; off; off >>= 1)
                ps += __shfl_xor_sync(0xffffffffu, ps, off);
            if (lane == 0) sRed4[w] = ps;
            __syncthreads();
            S = sRed4[0] + sRed4[1] + sRed4[2] + sRed4[3];   // exact ints
        }

        // --- phase B: row update (identical arithmetic) ---
        const float d1    = (lse - uy) - ltrg;
        const float sign1 = (d1 > 0.0f) ? 1.0f : ((d1 < 0.0f) ? -1.0f : 0.0f);
        const bool  isStar = (i == istar);
        const float c2 = BETA * S * M;

        // lazy jstar: only the star warp scans its registers (u unchanged
        // since the scan this replaces; identical two-stage selection)
        int jstar = -1;
        if (isStar) {
            float bb = -INFINITY; int jj = NC;
#pragma unroll
            for (int k = 0; k < 32; k++) {
                int j = k * 32 + lane;
                if (j < NC) { if (u[k] > bb) { bb = u[k]; jj = j; } }
            }
#pragma unroll
            for (int off = 16; off; off >>= 1) {
                float ov = __shfl_down_sync(0xffffffffu, bb, off);
                int   oj = __shfl_down_sync(0xffffffffu, jj, off);
                if (ov > bb || (ov == bb && oj < jj)) { bb = ov; jj = oj; }
            }
            jstar = __shfl_sync(0xffffffffu, jj, 0);
        }

        float bvn = -INFINITY;
        float uyNew = 0.0f;

#pragma unroll
        for (int kg = 0; kg < 4; kg++) {
            float2 mv[8];
            if (t > 1) {
#pragma unroll
                for (int q = 0; q < 8; q++) {
                    int j = (kg * 8 + q) * 32 + lane;
                    if (j < NC) mv[q] = mvrow[j];
                }
            }
#pragma unroll
            for (int q = 0; q < 8; q++) {
                const int k = kg * 8 + q;
                const int j = k * 32 + lane;
                if (j < NC) {
                    float s = expf(u[k] - lse);
                    float g = sign1 * (s - ((j == y) ? 1.0f : 0.0f));
                    if (isStar) g += c2 * (((j == jstar) ? 1.0f : 0.0f) - s);
                    float m, v;
                    if (t == 1) { m = 0.1f * g;                    v = 0.001f * g * g; }
                    else        { m = 0.9f * mv[q].x + 0.1f * g;
                                  v = 0.999f * mv[q].y + 0.001f * g * g; }
                    mvrow[j] = make_float2(m, v);
                    float upd  = (m * bc1) / (sqrtf(v * bc2) + EPS_F);
                    float unew = u[k] * DECAY - LR * upd;
                    u[k] = unew;
                    bvn = fmaxf(bvn, unew);       // max only (exact)
                    if (j == y) uyNew = unew;
                }
            }
        }

        // warp max reduce (order-independent, exact)
#pragma unroll
        for (int off = 16; off; off >>= 1)
            bvn = fmaxf(bvn, __shfl_xor_sync(0xffffffffu, bvn, off));

        float se2 = 0.0f;
#pragma unroll
        for (int k = 0; k < 32; k++) {
            int j = k * 32 + lane;
            if (j < NC) se2 += expf(u[k] - bvn);
        }
#pragma unroll
        for (int off = 16; off; off >>= 1) se2 += __shfl_xor_sync(0xffffffffu, se2, off);

        uyNew = __shfl_sync(0xffffffffu, uyNew, y & 31);

        lse = bvn + logf(se2);
        uy  = uyNew;

        if (t < 100) {
            if (lane == 0) sKey[w] = make_key(1.0f / se2, i);
            __syncthreads();
            if (tid == 0) {
                unsigned long long kk = sKey[0];
#pragma unroll
                for (int q = 1; q < 4; q++) if (sKey[q] > kk) kk = sKey[q];
                arrive_key(t + 1, kk);
            }
        }
    }

    // ---- final writeback ----
#pragma unroll
    for (int k = 0; k < 32; k++) {
        int j = k * 32 + lane;
        if (j < NC) Urow[j] = u[k];
    }
}

// =====================================================================
extern "C" void kernel_launch(void* const* d_in, const int* in_sizes, int n_in,
                              void* d_out, int out_size)
{
    const float* x = (const float*)d_in[0];
    const float* W = (const float*)d_in[1];
    const float* b = (const float*)d_in[2];
    float* U = (float*)d_out;

    // One-time: verify smem-m,v variant is fully co-resident (deadlock-proof).
    static int useSmem = -1;
    if (useSmem < 0) {
        cudaFuncSetAttribute(persist_steps<true>,
                             cudaFuncAttributePreferredSharedMemoryCarveout, 100);
        int occ = 0, sms = 0, dev = 0;
        cudaGetDevice(&dev);
        cudaDeviceGetAttribute(&sms, cudaDevAttrMultiProcessorCount, dev);
        cudaOccupancyMaxActiveBlocksPerMultiprocessor(
            &occ, persist_steps<true>, 128, 0);
        useSmem = (occ * sms >= NBLK) ? 1 : 0;
    }

    setup_kernel<<<26, 128>>>();
    dummy_kernel<<<1, 32>>>();                // capture slot #4 = persist_steps

    dim3 ggrid((NC + 63) / 64, NB / 64);      // (16, 64) = 1024 blocks
    sgemm_bias<<<ggrid, 256>>>(x, W, b, U);

    if (useSmem) persist_steps<true><<<NBLK, 128>>>(U);
    else         persist_steps<false><<<NBLK, 128>>>(U);
}

// round 15
// speedup vs baseline: 1.2626x; 1.2626x over previous
#include <cuda_runtime.h>
#include <math.h>

#define NB 4096
#define NC 1000
#define ND 2048
#define NBLK 1024
#define NMIR 32

#define TAU   6.0f
#define ALPHA 1.0f
#define BETA  5.0f
#define LR    0.1f
#define PI_F  3.14159265358979f
#define EPS_F 1e-8f
#define DECAY 0.999f   /* 1 - LR*WD */

// ---- scratch state (device globals: no allocation allowed) ----
__device__ float2 g_mv[NB * NC];     // only used by fallback variant
__device__ float  g_ptrg[NB];        // constant per row

struct KeySlot { unsigned long long k; unsigned long long pad[15]; }; // 128B
__device__ KeySlot g_key[104];
struct CntSlot { int c; int pad[31]; };                               // 128B
__device__ CntSlot g_cnt[104];
__device__ KeySlot g_mirror[104 * NMIR];   // parallel-written broadcast lines

// key = [pmax_bits:32 | (4095-row):12 | jmax:12]  (pmax>0 so bit order == value order)
__device__ __forceinline__ unsigned long long make_key(float pm, int row, int jm)
{
    return (((unsigned long long)__float_as_uint(pm)) << 24)
         | (((unsigned long long)(4095 - row)) << 12)
         | (unsigned long long)jm;
}

__device__ __forceinline__ void red_release_add1(int* p)
{
    asm volatile("red.release.gpu.global.add.s32 [%0], 1;" :: "l"(p) : "memory");
}
__device__ __forceinline__ int ld_acquire(const int* p)
{
    int v;
    asm volatile("ld.acquire.gpu.global.s32 %0, [%1];" : "=r"(v) : "l"(p) : "memory");
    return v;
}
__device__ __forceinline__ unsigned long long ld_acquire64(const unsigned long long* p)
{
    unsigned long long v;
    asm volatile("ld.acquire.gpu.global.u64 %0, [%1];" : "=l"(v) : "l"(p) : "memory");
    return v;
}
__device__ __forceinline__ void st_release64(unsigned long long* p, unsigned long long v)
{
    asm volatile("st.release.gpu.global.u64 [%0], %1;" :: "l"(p), "l"(v) : "memory");
}

// =====================================================================
// setup: zero key/counter/mirror slots (rerun every graph replay)
// =====================================================================
__global__ void setup_kernel()
{
    int t = blockIdx.x * blockDim.x + threadIdx.x;
    for (int s = t; s < 104 * NMIR; s += gridDim.x * blockDim.x)
        g_mirror[s].k = 0ull;
    if (t < 104) { g_key[t].k = 0ull; g_cnt[t].c = 0; }
}

// one dummy launch steers ncu's fixed capture slot (#4) onto persist_steps
__global__ void dummy_kernel() {}

// =====================================================================
// Barrier. Arrival: flat (PROVEN — atomicMax + RED on one pair of lines).
// Wait: blocks 0..31 poll the global counter (32 pollers, ~one per SM);
// each writes the final key to its OWN mirror line in parallel. Blocks
// >=32 poll mirror[bid&31] with BOUNDED spin; on exhaustion they fall
// back to the proven counter poll — wait cannot hang if the flat
// barrier is sound (measured at 2105us).
// =====================================================================
__device__ __forceinline__ void arrive_key(int t, unsigned long long kk)
{
    atomicMax(&g_key[t].k, kk);
    red_release_add1(&g_cnt[t].c);
}

__device__ __forceinline__ unsigned long long wait_key(int t, int bid)
{
    if (bid < NMIR) {
        while (ld_acquire(&g_cnt[t].c) < NBLK) __nanosleep(40);
        unsigned long long fk = ld_acquire64(&g_key[t].k);
        st_release64(&g_mirror[t * NMIR + bid].k, fk);   // parallel fanout
        return fk;
    } else {
        const unsigned long long* p = &g_mirror[t * NMIR + (bid & (NMIR - 1))].k;
        unsigned long long fk;
        int spins = 0;
        while ((fk = ld_acquire64(p)) == 0ull) {
            __nanosleep(40);
            if (++spins > 20000) {        // ~1ms: provably bounded fallback
                while (ld_acquire(&g_cnt[t].c) < NBLK) __nanosleep(40);
                fk = ld_acquire64(&g_key[t].k);
                break;
            }
        }
        return fk;
    }
}

// =====================================================================
// GEMM: z = x @ W + b. 64x64 tile, BK=16, 256 thr, 4x4/thr, double-buf.
// Measured 497us = 94% of scalar FFMA floor. DO NOT TOUCH.
// =====================================================================
__global__ __launch_bounds__(256) void sgemm_bias(
    const float* __restrict__ A, const float* __restrict__ B,
    const float* __restrict__ bias, float* __restrict__ C)
{
    __shared__ float As[2][16][64];
    __shared__ float Bs[2][16][64];

    const int tid = threadIdx.x;
    const int tx = tid & 15;
    const int ty = tid >> 4;
    const int rowBase = blockIdx.y * 64;
    const int colBase = blockIdx.x * 64;

    const int ar = tid >> 2;
    const int ak = (tid & 3) << 2;
    const int bk = tid >> 4;
    const int bc = (tid & 15) << 2;
    const int bgc = colBase + bc;

    float acc[4][4];
#pragma unroll
    for (int q = 0; q < 4; q++)
#pragma unroll
        for (int p = 0; p < 4; p++) acc[q][p] = 0.0f;

    {
        float4 av = *reinterpret_cast<const float4*>(
            &A[(size_t)(rowBase + ar) * ND + ak]);
        As[0][ak + 0][ar] = av.x; As[0][ak + 1][ar] = av.y;
        As[0][ak + 2][ar] = av.z; As[0][ak + 3][ar] = av.w;
        float4 bv = make_float4(0.f, 0.f, 0.f, 0.f);
        if (bgc < NC)
            bv = *reinterpret_cast<const float4*>(&B[(size_t)bk * NC + bgc]);
        *reinterpret_cast<float4*>(&Bs[0][bk][bc]) = bv;
    }
    __syncthreads();

    int buf = 0;
    for (int kt = 0; kt < ND / 16; kt++) {
        float4 pa, pb;
        const bool hasNext = (kt + 1 < ND / 16);
        if (hasNext) {
            int k0 = (kt + 1) * 16;
            pa = *reinterpret_cast<const float4*>(
                &A[(size_t)(rowBase + ar) * ND + k0 + ak]);
            pb = make_float4(0.f, 0.f, 0.f, 0.f);
            if (bgc < NC)
                pb = *reinterpret_cast<const float4*>(
                    &B[(size_t)(k0 + bk) * NC + bgc]);
        }

#pragma unroll
        for (int kk = 0; kk < 16; kk++) {
            float4 a4 = *reinterpret_cast<float4*>(&As[buf][kk][ty * 4]);
            float4 b4 = *reinterpret_cast<float4*>(&Bs[buf][kk][tx * 4]);
            float a[4] = {a4.x, a4.y, a4.z, a4.w};
            float bb[4] = {b4.x, b4.y, b4.z, b4.w};
#pragma unroll
            for (int q = 0; q < 4; q++)
#pragma unroll
                for (int p = 0; p < 4; p++)
                    acc[q][p] = fmaf(a[q], bb[p], acc[q][p]);
        }

        if (hasNext) {
            int nb = buf ^ 1;
            As[nb][ak + 0][ar] = pa.x; As[nb][ak + 1][ar] = pa.y;
            As[nb][ak + 2][ar] = pa.z; As[nb][ak + 3][ar] = pa.w;
            *reinterpret_cast<float4*>(&Bs[nb][bk][bc]) = pb;
            __syncthreads();
            buf = nb;
        }
    }

    const int cbase = colBase + tx * 4;
    if (cbase < NC) {
        float4 bv = *reinterpret_cast<const float4*>(&bias[cbase]);
#pragma unroll
        for (int q = 0; q < 4; q++) {
            int r = rowBase + ty * 4 + q;
            float4 o;
            o.x = acc[q][0] + bv.x; o.y = acc[q][1] + bv.y;
            o.z = acc[q][2] + bv.z; o.w = acc[q][3] + bv.w;
            *reinterpret_cast<float4*>(&C[(size_t)r * NC + cbase]) = o;
        }
    }
}

// =====================================================================
// Persistent kernel (template): init stats + 100 AdamW steps.
// EXACT 2105-benched body (eager jstar, original reductions).
// Warp-per-row, u in registers. SMEMV: m,v in shared; else gmem (L2).
// =====================================================================
template<bool SMEMV>
__global__ __launch_bounds__(128, 7) void persist_steps(float* __restrict__ U)
{
    __shared__ float2 smv[4][SMEMV ? NC : 1];
    __shared__ unsigned long long sKey[4];
    __shared__ unsigned long long sKeyFinal;
    __shared__ float  sRed4[4];
    __shared__ float2 sBC;

    const int tid  = threadIdx.x;
    const int lane = tid & 31;
    const int w    = tid >> 5;
    const int i    = blockIdx.x * 4 + w;
    const int bid  = blockIdx.x;

    float*  Urow  = U + (size_t)i * NC;
    float2* mvrow = SMEMV ? &smv[w][0] : (g_mv + (size_t)i * NC);

    // ---- load row into registers ----
    float u[32];
#pragma unroll
    for (int k = 0; k < 32; k++) {
        int j = k * 32 + lane;
        u[k] = (j < NC) ? Urow[j] : -INFINITY;
    }

    // ---- init stats (identical arithmetic to prior rounds) ----
    float bv = -INFINITY; int bj = NC;
#pragma unroll
    for (int k = 0; k < 32; k++) {
        int j = k * 32 + lane;
        if (j < NC) { if (u[k] > bv) { bv = u[k]; bj = j; } }
    }
#pragma unroll
    for (int off = 16; off; off >>= 1) {
        float ov = __shfl_down_sync(0xffffffffu, bv, off);
        int   oj = __shfl_down_sync(0xffffffffu, bj, off);
        if (ov > bv || (ov == bv && oj < bj)) { bv = ov; bj = oj; }
    }
    bv = __shfl_sync(0xffffffffu, bv, 0);
    bj = __shfl_sync(0xffffffffu, bj, 0);

    float se = 0.0f;
#pragma unroll
    for (int k = 0; k < 32; k++) {
        int j = k * 32 + lane;
        if (j < NC) se += expf(u[k] - bv);
    }
#pragma unroll
    for (int off = 16; off; off >>= 1) se += __shfl_xor_sync(0xffffffffu, se, off);

    float l_org = logf(se);
    float l_atr = (floorf(l_org / TAU) + 0.5f) * TAU;
    const float ltrg = l_org - ALPHA * TAU *
                       sinf(PI_F * (1.0f - 2.0f * (l_org - l_atr) / TAU));
    float pm  = 1.0f / se;
    float lse = bv + l_org;     // lane-uniform
    float uy  = bv;             // z[i, y] = rowmax
    const int y = bj;

    if (lane == 0) {
        g_ptrg[i] = pm;
        sKey[w]   = make_key(pm, i, bj);
    }
    __syncthreads();
    if (tid == 0) {
        unsigned long long kk = sKey[0];
#pragma unroll
        for (int q = 1; q < 4; q++) if (sKey[q] > kk) kk = sKey[q];
        arrive_key(1, kk);   // release orders the g_ptrg store too
    }

    // bias-correction running products (tid 0 only; bitwise-proven)
    double p1 = 1.0, p2 = 1.0;

    // =================== step loop ===================
    for (int t = 1; t <= 100; t++) {
        if (tid == 0) {
            sKeyFinal = wait_key(t, bid);
            p1 *= 0.9; p2 *= 0.999;
            sBC = make_float2((float)(1.0 / (1.0 - p1)),
                              (float)(1.0 / (1.0 - p2)));
        }
        __syncthreads();

        const unsigned long long key = sKeyFinal;
        const float M     = __uint_as_float((unsigned int)(key >> 24));
        const int   istar = 4095 - (int)((key >> 12) & 0xFFF);
        const int   jstar = (int)(key & 0xFFF);
        const float bc1 = sBC.x, bc2 = sBC.y;

        // --- S only needed by the star row's block (ptrg L1-resident) ---
        const bool starBlk = ((istar >> 2) == bid);
        float S = 0.0f;
        if (starBlk) {
            float ps = 0.0f;
            for (int r = tid; r < NB; r += 128) {
                float d = M - g_ptrg[r];
                ps += (d > 0.0f) ? 1.0f : ((d < 0.0f) ? -1.0f : 0.0f);
            }
#pragma unroll
            for (int off = 16; off; off >>= 1)
                ps += __shfl_xor_sync(0xffffffffu, ps, off);
            if (lane == 0) sRed4[w] = ps;
            __syncthreads();
            S = sRed4[0] + sRed4[1] + sRed4[2] + sRed4[3];   // exact ints
        }

        // --- phase B: row update (identical arithmetic) ---
        const float d1    = (lse - uy) - ltrg;
        const float sign1 = (d1 > 0.0f) ? 1.0f : ((d1 < 0.0f) ? -1.0f : 0.0f);
        const bool  isStar = (i == istar);
        const float c2 = BETA * S * M;

        float bvn = -INFINITY; int bjn = NC;
        float uyNew = 0.0f;

#pragma unroll
        for (int kg = 0; kg < 4; kg++) {
            float2 mv[8];
            if (t > 1) {
#pragma unroll
                for (int q = 0; q < 8; q++) {
                    int j = (kg * 8 + q) * 32 + lane;
                    if (j < NC) mv[q] = mvrow[j];
                }
            }
#pragma unroll
            for (int q = 0; q < 8; q++) {
                const int k = kg * 8 + q;
                const int j = k * 32 + lane;
                if (j < NC) {
                    float s = expf(u[k] - lse);
                    float g = sign1 * (s - ((j == y) ? 1.0f : 0.0f));
                    if (isStar) g += c2 * (((j == jstar) ? 1.0f : 0.0f) - s);
                    float m, v;
                    if (t == 1) { m = 0.1f * g;                    v = 0.001f * g * g; }
                    else        { m = 0.9f * mv[q].x + 0.1f * g;
                                  v = 0.999f * mv[q].y + 0.001f * g * g; }
                    mvrow[j] = make_float2(m, v);
                    float upd  = (m * bc1) / (sqrtf(v * bc2) + EPS_F);
                    float unew = u[k] * DECAY - LR * upd;
                    u[k] = unew;
                    if (unew > bvn) { bvn = unew; bjn = j; }
                    if (j == y) uyNew = unew;
                }
            }
        }

#pragma unroll
        for (int off = 16; off; off >>= 1) {
            float ov = __shfl_down_sync(0xffffffffu, bvn, off);
            int   oj = __shfl_down_sync(0xffffffffu, bjn, off);
            if (ov > bvn || (ov == bvn && oj < bjn)) { bvn = ov; bjn = oj; }
        }
        bvn = __shfl_sync(0xffffffffu, bvn, 0);
        bjn = __shfl_sync(0xffffffffu, bjn, 0);

        float se2 = 0.0f;
#pragma unroll
        for (int k = 0; k < 32; k++) {
            int j = k * 32 + lane;
            if (j < NC) se2 += expf(u[k] - bvn);
        }
#pragma unroll
        for (int off = 16; off; off >>= 1) se2 += __shfl_xor_sync(0xffffffffu, se2, off);

        uyNew = __shfl_sync(0xffffffffu, uyNew, y & 31);

        lse = bvn + logf(se2);
        uy  = uyNew;

        if (t < 100) {
            if (lane == 0) sKey[w] = make_key(1.0f / se2, i, bjn);
            __syncthreads();
            if (tid == 0) {
                unsigned long long kk = sKey[0];
#pragma unroll
                for (int q = 1; q < 4; q++) if (sKey[q] > kk) kk = sKey[q];
                arrive_key(t + 1, kk);
            }
        }
    }

    // ---- final writeback ----
#pragma unroll
    for (int k = 0; k < 32; k++) {
        int j = k * 32 + lane;
        if (j < NC) Urow[j] = u[k];
    }
}

// =====================================================================
extern "C" void kernel_launch(void* const* d_in, const int* in_sizes, int n_in,
                              void* d_out, int out_size)
{
    const float* x = (const float*)d_in[0];
    const float* W = (const float*)d_in[1];
    const float* b = (const float*)d_in[2];
    float* U = (float*)d_out;

    // One-time: verify smem-m,v variant is fully co-resident (deadlock-proof).
    static int useSmem = -1;
    if (useSmem < 0) {
        cudaFuncSetAttribute(persist_steps<true>,
                             cudaFuncAttributePreferredSharedMemoryCarveout, 100);
        int occ = 0, sms = 0, dev = 0;
        cudaGetDevice(&dev);
        cudaDeviceGetAttribute(&sms, cudaDevAttrMultiProcessorCount, dev);
        cudaOccupancyMaxActiveBlocksPerMultiprocessor(
            &occ, persist_steps<true>, 128, 0);
        useSmem = (occ * sms >= NBLK) ? 1 : 0;
    }

    setup_kernel<<<26, 128>>>();
    dummy_kernel<<<1, 32>>>();                // capture slot #4 = persist_steps

    dim3 ggrid((NC + 63) / 64, NB / 64);      // (16, 64) = 1024 blocks
    sgemm_bias<<<ggrid, 256>>>(x, W, b, U);

    if (useSmem) persist_steps<true><<<NBLK, 128>>>(U);
    else         persist_steps<false><<<NBLK, 128>>>(U);
}

// round 16
// speedup vs baseline: 1.3400x; 1.0613x over previous
#include <cuda_runtime.h>
#include <math.h>

#define NB 4096
#define NC 1000
#define ND 2048
#define NBLK 1024

#define TAU   6.0f
#define ALPHA 1.0f
#define BETA  5.0f
#define LR    0.1f
#define PI_F  3.14159265358979f
#define EPS_F 1e-8f
#define DECAY 0.999f   /* 1 - LR*WD */

// ---- scratch state (device globals: no allocation allowed) ----
__device__ float2 g_mv[NB * NC];     // only used by fallback variant
__device__ float  g_ptrg[NB];        // constant per row

struct KeySlot { unsigned long long k; unsigned long long pad[15]; }; // 128B
__device__ KeySlot g_key[104];
struct CntSlot { int c; int pad[31]; };                               // 128B
__device__ CntSlot g_cnt[104];

// key = [pmax_bits:32 | (4095-row):12 | jmax:12]  (pmax>0 so bit order == value order)
__device__ __forceinline__ unsigned long long make_key(float pm, int row, int jm)
{
    return (((unsigned long long)__float_as_uint(pm)) << 24)
         | (((unsigned long long)(4095 - row)) << 12)
         | (unsigned long long)jm;
}

__device__ __forceinline__ void red_release_add1(int* p)
{
    asm volatile("red.release.gpu.global.add.s32 [%0], 1;" :: "l"(p) : "memory");
}
__device__ __forceinline__ int ld_acquire(const int* p)
{
    int v;
    asm volatile("ld.acquire.gpu.global.s32 %0, [%1];" : "=r"(v) : "l"(p) : "memory");
    return v;
}

// =====================================================================
// setup: zero key/counter slots (rerun every graph replay)
// =====================================================================
__global__ void setup_kernel()
{
    int t = threadIdx.x;
    if (t < 104) { g_key[t].k = 0ull; g_cnt[t].c = 0; }
}

// one dummy launch steers ncu's fixed capture slot (#4) onto persist_steps
__global__ void dummy_kernel() {}

// =====================================================================
// GEMM: z = x @ W + b. 64x64 tile, BK=16, 256 thr, 4x4/thr, double-buf.
// Measured 497us = 94% of scalar FFMA floor. DO NOT TOUCH.
// =====================================================================
__global__ __launch_bounds__(256) void sgemm_bias(
    const float* __restrict__ A, const float* __restrict__ B,
    const float* __restrict__ bias, float* __restrict__ C)
{
    __shared__ float As[2][16][64];
    __shared__ float Bs[2][16][64];

    const int tid = threadIdx.x;
    const int tx = tid & 15;
    const int ty = tid >> 4;
    const int rowBase = blockIdx.y * 64;
    const int colBase = blockIdx.x * 64;

    const int ar = tid >> 2;
    const int ak = (tid & 3) << 2;
    const int bk = tid >> 4;
    const int bc = (tid & 15) << 2;
    const int bgc = colBase + bc;

    float acc[4][4];
#pragma unroll
    for (int q = 0; q < 4; q++)
#pragma unroll
        for (int p = 0; p < 4; p++) acc[q][p] = 0.0f;

    {
        float4 av = *reinterpret_cast<const float4*>(
            &A[(size_t)(rowBase + ar) * ND + ak]);
        As[0][ak + 0][ar] = av.x; As[0][ak + 1][ar] = av.y;
        As[0][ak + 2][ar] = av.z; As[0][ak + 3][ar] = av.w;
        float4 bv = make_float4(0.f, 0.f, 0.f, 0.f);
        if (bgc < NC)
            bv = *reinterpret_cast<const float4*>(&B[(size_t)bk * NC + bgc]);
        *reinterpret_cast<float4*>(&Bs[0][bk][bc]) = bv;
    }
    __syncthreads();

    int buf = 0;
    for (int kt = 0; kt < ND / 16; kt++) {
        float4 pa, pb;
        const bool hasNext = (kt + 1 < ND / 16);
        if (hasNext) {
            int k0 = (kt + 1) * 16;
            pa = *reinterpret_cast<const float4*>(
                &A[(size_t)(rowBase + ar) * ND + k0 + ak]);
            pb = make_float4(0.f, 0.f, 0.f, 0.f);
            if (bgc < NC)
                pb = *reinterpret_cast<const float4*>(
                    &B[(size_t)(k0 + bk) * NC + bgc]);
        }

#pragma unroll
        for (int kk = 0; kk < 16; kk++) {
            float4 a4 = *reinterpret_cast<float4*>(&As[buf][kk][ty * 4]);
            float4 b4 = *reinterpret_cast<float4*>(&Bs[buf][kk][tx * 4]);
            float a[4] = {a4.x, a4.y, a4.z, a4.w};
            float bb[4] = {b4.x, b4.y, b4.z, b4.w};
#pragma unroll
            for (int q = 0; q < 4; q++)
#pragma unroll
                for (int p = 0; p < 4; p++)
                    acc[q][p] = fmaf(a[q], bb[p], acc[q][p]);
        }

        if (hasNext) {
            int nb = buf ^ 1;
            As[nb][ak + 0][ar] = pa.x; As[nb][ak + 1][ar] = pa.y;
            As[nb][ak + 2][ar] = pa.z; As[nb][ak + 3][ar] = pa.w;
            *reinterpret_cast<float4*>(&Bs[nb][bk][bc]) = pb;
            __syncthreads();
            buf = nb;
        }
    }

    const int cbase = colBase + tx * 4;
    if (cbase < NC) {
        float4 bv = *reinterpret_cast<const float4*>(&bias[cbase]);
#pragma unroll
        for (int q = 0; q < 4; q++) {
            int r = rowBase + ty * 4 + q;
            float4 o;
            o.x = acc[q][0] + bv.x; o.y = acc[q][1] + bv.y;
            o.z = acc[q][2] + bv.z; o.w = acc[q][3] + bv.w;
            *reinterpret_cast<float4*>(&C[(size_t)r * NC + cbase]) = o;
        }
    }
}

// =====================================================================
// Persistent kernel (template): init stats + 100 AdamW steps.
// EXACT 2105-benched body + flat barrier; ONE change: capped exponential
// backoff in the counter poll (40->320ns).
// Warp-per-row, u in registers. SMEMV: m,v in shared; else gmem (L2).
// =====================================================================
template<bool SMEMV>
__global__ __launch_bounds__(128, 7) void persist_steps(float* __restrict__ U)
{
    __shared__ float2 smv[4][SMEMV ? NC : 1];
    __shared__ unsigned long long sKey[4];
    __shared__ float  sRed4[4];
    __shared__ float2 sBC;

    const int tid  = threadIdx.x;
    const int lane = tid & 31;
    const int w    = tid >> 5;
    const int i    = blockIdx.x * 4 + w;

    float*  Urow  = U + (size_t)i * NC;
    float2* mvrow = SMEMV ? &smv[w][0] : (g_mv + (size_t)i * NC);

    // ---- load row into registers ----
    float u[32];
#pragma unroll
    for (int k = 0; k < 32; k++) {
        int j = k * 32 + lane;
        u[k] = (j < NC) ? Urow[j] : -INFINITY;
    }

    // ---- init stats (identical arithmetic to prior rounds) ----
    float bv = -INFINITY; int bj = NC;
#pragma unroll
    for (int k = 0; k < 32; k++) {
        int j = k * 32 + lane;
        if (j < NC) { if (u[k] > bv) { bv = u[k]; bj = j; } }
    }
#pragma unroll
    for (int off = 16; off; off >>= 1) {
        float ov = __shfl_down_sync(0xffffffffu, bv, off);
        int   oj = __shfl_down_sync(0xffffffffu, bj, off);
        if (ov > bv || (ov == bv && oj < bj)) { bv = ov; bj = oj; }
    }
    bv = __shfl_sync(0xffffffffu, bv, 0);
    bj = __shfl_sync(0xffffffffu, bj, 0);

    float se = 0.0f;
#pragma unroll
    for (int k = 0; k < 32; k++) {
        int j = k * 32 + lane;
        if (j < NC) se += expf(u[k] - bv);
    }
#pragma unroll
    for (int off = 16; off; off >>= 1) se += __shfl_xor_sync(0xffffffffu, se, off);

    float l_org = logf(se);
    float l_atr = (floorf(l_org / TAU) + 0.5f) * TAU;
    const float ltrg = l_org - ALPHA * TAU *
                       sinf(PI_F * (1.0f - 2.0f * (l_org - l_atr) / TAU));
    float pm  = 1.0f / se;
    float lse = bv + l_org;     // lane-uniform
    float uy  = bv;             // z[i, y] = rowmax
    const int y = bj;

    if (lane == 0) {
        g_ptrg[i] = pm;
        sKey[w]   = make_key(pm, i, bj);
    }
    __syncthreads();
    if (tid == 0) {
        unsigned long long kk = sKey[0];
#pragma unroll
        for (int q = 1; q < 4; q++) if (sKey[q] > kk) kk = sKey[q];
        atomicMax(&g_key[1].k, kk);
        red_release_add1(&g_cnt[1].c);   // orders ptrg store + atomicMax
    }

    // bias-correction running products (tid 0 only; bitwise-proven)
    double p1 = 1.0, p2 = 1.0;

    // =================== step loop ===================
    for (int t = 1; t <= 100; t++) {
        // wait for key_t final (capped exponential backoff — the one change)
        if (tid == 0) {
            unsigned ns = 40;
            while (ld_acquire(&g_cnt[t].c) < NBLK) {
                __nanosleep(ns);
                ns = (ns < 320u) ? (ns << 1) : 320u;
            }
            p1 *= 0.9; p2 *= 0.999;
            sBC = make_float2((float)(1.0 / (1.0 - p1)),
                              (float)(1.0 / (1.0 - p2)));
        }
        __syncthreads();

        const unsigned long long key = g_key[t].k;
        const float M     = __uint_as_float((unsigned int)(key >> 24));
        const int   istar = 4095 - (int)((key >> 12) & 0xFFF);
        const int   jstar = (int)(key & 0xFFF);
        const float bc1 = sBC.x, bc2 = sBC.y;

        // --- S only needed by the star row's block (ptrg L1-resident) ---
        const bool starBlk = ((istar >> 2) == (int)blockIdx.x);
        float S = 0.0f;
        if (starBlk) {
            float ps = 0.0f;
            for (int r = tid; r < NB; r += 128) {
                float d = M - g_ptrg[r];
                ps += (d > 0.0f) ? 1.0f : ((d < 0.0f) ? -1.0f : 0.0f);
            }
#pragma unroll
            for (int off = 16; off; off >>= 1)
                ps += __shfl_xor_sync(0xffffffffu, ps, off);
            if (lane == 0) sRed4[w] = ps;
            __syncthreads();
            S = sRed4[0] + sRed4[1] + sRed4[2] + sRed4[3];   // exact ints
        }

        // --- phase B: row update (identical arithmetic) ---
        const float d1    = (lse - uy) - ltrg;
        const float sign1 = (d1 > 0.0f) ? 1.0f : ((d1 < 0.0f) ? -1.0f : 0.0f);
        const bool  isStar = (i == istar);
        const float c2 = BETA * S * M;

        float bvn = -INFINITY; int bjn = NC;
        float uyNew = 0.0f;

#pragma unroll
        for (int kg = 0; kg < 4; kg++) {
            float2 mv[8];
            if (t > 1) {
#pragma unroll
                for (int q = 0; q < 8; q++) {
                    int j = (kg * 8 + q) * 32 + lane;
                    if (j < NC) mv[q] = mvrow[j];
                }
            }
#pragma unroll
            for (int q = 0; q < 8; q++) {
                const int k = kg * 8 + q;
                const int j = k * 32 + lane;
                if (j < NC) {
                    float s = expf(u[k] - lse);
                    float g = sign1 * (s - ((j == y) ? 1.0f : 0.0f));
                    if (isStar) g += c2 * (((j == jstar) ? 1.0f : 0.0f) - s);
                    float m, v;
                    if (t == 1) { m = 0.1f * g;                    v = 0.001f * g * g; }
                    else        { m = 0.9f * mv[q].x + 0.1f * g;
                                  v = 0.999f * mv[q].y + 0.001f * g * g; }
                    mvrow[j] = make_float2(m, v);
                    float upd  = (m * bc1) / (sqrtf(v * bc2) + EPS_F);
                    float unew = u[k] * DECAY - LR * upd;
                    u[k] = unew;
                    if (unew > bvn) { bvn = unew; bjn = j; }
                    if (j == y) uyNew = unew;
                }
            }
        }

#pragma unroll
        for (int off = 16; off; off >>= 1) {
            float ov = __shfl_down_sync(0xffffffffu, bvn, off);
            int   oj = __shfl_down_sync(0xffffffffu, bjn, off);
            if (ov > bvn || (ov == bvn && oj < bjn)) { bvn = ov; bjn = oj; }
        }
        bvn = __shfl_sync(0xffffffffu, bvn, 0);
        bjn = __shfl_sync(0xffffffffu, bjn, 0);

        float se2 = 0.0f;
#pragma unroll
        for (int k = 0; k < 32; k++) {
            int j = k * 32 + lane;
            if (j < NC) se2 += expf(u[k] - bvn);
        }
#pragma unroll
        for (int off = 16; off; off >>= 1) se2 += __shfl_xor_sync(0xffffffffu, se2, off);

        uyNew = __shfl_sync(0xffffffffu, uyNew, y & 31);

        lse = bvn + logf(se2);
        uy  = uyNew;

        if (t < 100) {
            if (lane == 0) sKey[w] = make_key(1.0f / se2, i, bjn);
            __syncthreads();
            if (tid == 0) {
                unsigned long long kk = sKey[0];
#pragma unroll
                for (int q = 1; q < 4; q++) if (sKey[q] > kk) kk = sKey[q];
                atomicMax(&g_key[t + 1].k, kk);
                red_release_add1(&g_cnt[t + 1].c);
            }
        }
    }

    // ---- final writeback ----
#pragma unroll
    for (int k = 0; k < 32; k++) {
        int j = k * 32 + lane;
        if (j < NC) Urow[j] = u[k];
    }
}

// =====================================================================
extern "C" void kernel_launch(void* const* d_in, const int* in_sizes, int n_in,
                              void* d_out, int out_size)
{
    const float* x = (const float*)d_in[0];
    const float* W = (const float*)d_in[1];
    const float* b = (const float*)d_in[2];
    float* U = (float*)d_out;

    // One-time: verify smem-m,v variant is fully co-resident (deadlock-proof).
    static int useSmem = -1;
    if (useSmem < 0) {
        cudaFuncSetAttribute(persist_steps<true>,
                             cudaFuncAttributePreferredSharedMemoryCarveout, 100);
        int occ = 0, sms = 0, dev = 0;
        cudaGetDevice(&dev);
        cudaDeviceGetAttribute(&sms, cudaDevAttrMultiProcessorCount, dev);
        cudaOccupancyMaxActiveBlocksPerMultiprocessor(
            &occ, persist_steps<true>, 128, 0);
        useSmem = (occ * sms >= NBLK) ? 1 : 0;
    }

    setup_kernel<<<1, 128>>>();
    dummy_kernel<<<1, 32>>>();                // capture slot #4 = persist_steps

    dim3 ggrid((NC + 63) / 64, NB / 64);      // (16, 64) = 1024 blocks
    sgemm_bias<<<ggrid, 256>>>(x, W, b, U);

    if (useSmem) persist_steps<true><<<NBLK, 128>>>(U);
    else         persist_steps<false><<<NBLK, 128>>>(U);
}

// round 17
// speedup vs baseline: 1.3502x; 1.0076x over previous
#include <cuda_runtime.h>
#include <math.h>

#define NB 4096
#define NC 1000
#define ND 2048
#define NBLK 1024

#define TAU   6.0f
#define ALPHA 1.0f
#define BETA  5.0f
#define LR    0.1f
#define PI_F  3.14159265358979f
#define EPS_F 1e-8f
#define DECAY 0.999f   /* 1 - LR*WD */

// ---- scratch state (device globals: no allocation allowed) ----
__device__ float2 g_mv[NB * NC];     // only used by fallback variant
__device__ float  g_ptrg[NB];        // constant per row

struct KeySlot { unsigned long long k; unsigned long long pad[15]; }; // 128B
__device__ KeySlot g_key[104];
struct CntSlot { int c; int pad[31]; };                               // 128B
__device__ CntSlot g_cnt[104];

// key = [pmax_bits:32 | (4095-row):12 | jmax:12]  (pmax>0 so bit order == value order)
__device__ __forceinline__ unsigned long long make_key(float pm, int row, int jm)
{
    return (((unsigned long long)__float_as_uint(pm)) << 24)
         | (((unsigned long long)(4095 - row)) << 12)
         | (unsigned long long)jm;
}

__device__ __forceinline__ void red_release_add1(int* p)
{
    asm volatile("red.release.gpu.global.add.s32 [%0], 1;" :: "l"(p) : "memory");
}
__device__ __forceinline__ int ld_relaxed(const int* p)
{
    int v;
    asm volatile("ld.relaxed.gpu.global.s32 %0, [%1];" : "=r"(v) : "l"(p) : "memory");
    return v;
}
__device__ __forceinline__ int ld_acquire(const int* p)
{
    int v;
    asm volatile("ld.acquire.gpu.global.s32 %0, [%1];" : "=r"(v) : "l"(p) : "memory");
    return v;
}

// =====================================================================
// GEMM: z = x @ W + b. 64x64 tile, BK=16, 256 thr, 4x4/thr, double-buf.
// Measured 497us = 94% of scalar FFMA floor. Arithmetic DO NOT TOUCH.
// Also zeroes barrier state each replay (proven R6-R8 pattern).
// =====================================================================
__global__ __launch_bounds__(256) void sgemm_bias(
    const float* __restrict__ A, const float* __restrict__ B,
    const float* __restrict__ bias, float* __restrict__ C)
{
    __shared__ float As[2][16][64];
    __shared__ float Bs[2][16][64];

    const int tid = threadIdx.x;

    // ---- zero barrier state (ordered before persist by stream order) ----
    {
        int s = blockIdx.x * 256 + tid;      // blockIdx.x in [0,16)
        if (s < 104) { g_key[s].k = 0ull; g_cnt[s].c = 0; }
    }

    const int tx = tid & 15;
    const int ty = tid >> 4;
    const int rowBase = blockIdx.y * 64;
    const int colBase = blockIdx.x * 64;

    const int ar = tid >> 2;
    const int ak = (tid & 3) << 2;
    const int bk = tid >> 4;
    const int bc = (tid & 15) << 2;
    const int bgc = colBase + bc;

    float acc[4][4];
#pragma unroll
    for (int q = 0; q < 4; q++)
#pragma unroll
        for (int p = 0; p < 4; p++) acc[q][p] = 0.0f;

    {
        float4 av = *reinterpret_cast<const float4*>(
            &A[(size_t)(rowBase + ar) * ND + ak]);
        As[0][ak + 0][ar] = av.x; As[0][ak + 1][ar] = av.y;
        As[0][ak + 2][ar] = av.z; As[0][ak + 3][ar] = av.w;
        float4 bv = make_float4(0.f, 0.f, 0.f, 0.f);
        if (bgc < NC)
            bv = *reinterpret_cast<const float4*>(&B[(size_t)bk * NC + bgc]);
        *reinterpret_cast<float4*>(&Bs[0][bk][bc]) = bv;
    }
    __syncthreads();

    int buf = 0;
    for (int kt = 0; kt < ND / 16; kt++) {
        float4 pa, pb;
        const bool hasNext = (kt + 1 < ND / 16);
        if (hasNext) {
            int k0 = (kt + 1) * 16;
            pa = *reinterpret_cast<const float4*>(
                &A[(size_t)(rowBase + ar) * ND + k0 + ak]);
            pb = make_float4(0.f, 0.f, 0.f, 0.f);
            if (bgc < NC)
                pb = *reinterpret_cast<const float4*>(
                    &B[(size_t)(k0 + bk) * NC + bgc]);
        }

#pragma unroll
        for (int kk = 0; kk < 16; kk++) {
            float4 a4 = *reinterpret_cast<float4*>(&As[buf][kk][ty * 4]);
            float4 b4 = *reinterpret_cast<float4*>(&Bs[buf][kk][tx * 4]);
            float a[4] = {a4.x, a4.y, a4.z, a4.w};
            float bb[4] = {b4.x, b4.y, b4.z, b4.w};
#pragma unroll
            for (int q = 0; q < 4; q++)
#pragma unroll
                for (int p = 0; p < 4; p++)
                    acc[q][p] = fmaf(a[q], bb[p], acc[q][p]);
        }

        if (hasNext) {
            int nb = buf ^ 1;
            As[nb][ak + 0][ar] = pa.x; As[nb][ak + 1][ar] = pa.y;
            As[nb][ak + 2][ar] = pa.z; As[nb][ak + 3][ar] = pa.w;
            *reinterpret_cast<float4*>(&Bs[nb][bk][bc]) = pb;
            __syncthreads();
            buf = nb;
        }
    }

    const int cbase = colBase + tx * 4;
    if (cbase < NC) {
        float4 bv = *reinterpret_cast<const float4*>(&bias[cbase]);
#pragma unroll
        for (int q = 0; q < 4; q++) {
            int r = rowBase + ty * 4 + q;
            float4 o;
            o.x = acc[q][0] + bv.x; o.y = acc[q][1] + bv.y;
            o.z = acc[q][2] + bv.z; o.w = acc[q][3] + bv.w;
            *reinterpret_cast<float4*>(&C[(size_t)r * NC + cbase]) = o;
        }
    }
}

// =====================================================================
// Persistent kernel (template): init stats + 100 AdamW steps.
// EXACT 2055-benched body + flat barrier. Changes this round:
// relaxed poll + final acquire; backoff cap 320 -> 640ns.
// Warp-per-row, u in registers. SMEMV: m,v in shared; else gmem (L2).
// =====================================================================
template<bool SMEMV>
__global__ __launch_bounds__(128, 7) void persist_steps(float* __restrict__ U)
{
    __shared__ float2 smv[4][SMEMV ? NC : 1];
    __shared__ unsigned long long sKey[4];
    __shared__ float  sRed4[4];
    __shared__ float2 sBC;

    const int tid  = threadIdx.x;
    const int lane = tid & 31;
    const int w    = tid >> 5;
    const int i    = blockIdx.x * 4 + w;

    float*  Urow  = U + (size_t)i * NC;
    float2* mvrow = SMEMV ? &smv[w][0] : (g_mv + (size_t)i * NC);

    // ---- load row into registers ----
    float u[32];
#pragma unroll
    for (int k = 0; k < 32; k++) {
        int j = k * 32 + lane;
        u[k] = (j < NC) ? Urow[j] : -INFINITY;
    }

    // ---- init stats (identical arithmetic to prior rounds) ----
    float bv = -INFINITY; int bj = NC;
#pragma unroll
    for (int k = 0; k < 32; k++) {
        int j = k * 32 + lane;
        if (j < NC) { if (u[k] > bv) { bv = u[k]; bj = j; } }
    }
#pragma unroll
    for (int off = 16; off; off >>= 1) {
        float ov = __shfl_down_sync(0xffffffffu, bv, off);
        int   oj = __shfl_down_sync(0xffffffffu, bj, off);
        if (ov > bv || (ov == bv && oj < bj)) { bv = ov; bj = oj; }
    }
    bv = __shfl_sync(0xffffffffu, bv, 0);
    bj = __shfl_sync(0xffffffffu, bj, 0);

    float se = 0.0f;
#pragma unroll
    for (int k = 0; k < 32; k++) {
        int j = k * 32 + lane;
        if (j < NC) se += expf(u[k] - bv);
    }
#pragma unroll
    for (int off = 16; off; off >>= 1) se += __shfl_xor_sync(0xffffffffu, se, off);

    float l_org = logf(se);
    float l_atr = (floorf(l_org / TAU) + 0.5f) * TAU;
    const float ltrg = l_org - ALPHA * TAU *
                       sinf(PI_F * (1.0f - 2.0f * (l_org - l_atr) / TAU));
    float pm  = 1.0f / se;
    float lse = bv + l_org;     // lane-uniform
    float uy  = bv;             // z[i, y] = rowmax
    const int y = bj;

    if (lane == 0) {
        g_ptrg[i] = pm;
        sKey[w]   = make_key(pm, i, bj);
    }
    __syncthreads();
    if (tid == 0) {
        unsigned long long kk = sKey[0];
#pragma unroll
        for (int q = 1; q < 4; q++) if (sKey[q] > kk) kk = sKey[q];
        atomicMax(&g_key[1].k, kk);
        red_release_add1(&g_cnt[1].c);   // orders ptrg store + atomicMax
    }

    // bias-correction running products (tid 0 only; bitwise-proven)
    double p1 = 1.0, p2 = 1.0;

    // =================== step loop ===================
    for (int t = 1; t <= 100; t++) {
        // wait for key_t final: relaxed poll + capped backoff, acquire once
        if (tid == 0) {
            unsigned ns = 40;
            while (ld_relaxed(&g_cnt[t].c) < NBLK) {
                __nanosleep(ns);
                ns = (ns < 640u) ? (ns << 1) : 640u;
            }
            (void)ld_acquire(&g_cnt[t].c);   // order the key/ptrg reads
            p1 *= 0.9; p2 *= 0.999;
            sBC = make_float2((float)(1.0 / (1.0 - p1)),
                              (float)(1.0 / (1.0 - p2)));
        }
        __syncthreads();

        const unsigned long long key = g_key[t].k;
        const float M     = __uint_as_float((unsigned int)(key >> 24));
        const int   istar = 4095 - (int)((key >> 12) & 0xFFF);
        const int   jstar = (int)(key & 0xFFF);
        const float bc1 = sBC.x, bc2 = sBC.y;

        // --- S only needed by the star row's block (ptrg L1-resident) ---
        const bool starBlk = ((istar >> 2) == (int)blockIdx.x);
        float S = 0.0f;
        if (starBlk) {
            float ps = 0.0f;
            for (int r = tid; r < NB; r += 128) {
                float d = M - g_ptrg[r];
                ps += (d > 0.0f) ? 1.0f : ((d < 0.0f) ? -1.0f : 0.0f);
            }
#pragma unroll
            for (int off = 16; off; off >>= 1)
                ps += __shfl_xor_sync(0xffffffffu, ps, off);
            if (lane == 0) sRed4[w] = ps;
            __syncthreads();
            S = sRed4[0] + sRed4[1] + sRed4[2] + sRed4[3];   // exact ints
        }

        // --- phase B: row update (identical arithmetic) ---
        const float d1    = (lse - uy) - ltrg;
        const float sign1 = (d1 > 0.0f) ? 1.0f : ((d1 < 0.0f) ? -1.0f : 0.0f);
        const bool  isStar = (i == istar);
        const float c2 = BETA * S * M;

        float bvn = -INFINITY; int bjn = NC;
        float uyNew = 0.0f;

#pragma unroll
        for (int kg = 0; kg < 4; kg++) {
            float2 mv[8];
            if (t > 1) {
#pragma unroll
                for (int q = 0; q < 8; q++) {
                    int j = (kg * 8 + q) * 32 + lane;
                    if (j < NC) mv[q] = mvrow[j];
                }
            }
#pragma unroll
            for (int q = 0; q < 8; q++) {
                const int k = kg * 8 + q;
                const int j = k * 32 + lane;
                if (j < NC) {
                    float s = expf(u[k] - lse);
                    float g = sign1 * (s - ((j == y) ? 1.0f : 0.0f));
                    if (isStar) g += c2 * (((j == jstar) ? 1.0f : 0.0f) - s);
                    float m, v;
                    if (t == 1) { m = 0.1f * g;                    v = 0.001f * g * g; }
                    else        { m = 0.9f * mv[q].x + 0.1f * g;
                                  v = 0.999f * mv[q].y + 0.001f * g * g; }
                    mvrow[j] = make_float2(m, v);
                    float upd  = (m * bc1) / (sqrtf(v * bc2) + EPS_F);
                    float unew = u[k] * DECAY - LR * upd;
                    u[k] = unew;
                    if (unew > bvn) { bvn = unew; bjn = j; }
                    if (j == y) uyNew = unew;
                }
            }
        }

#pragma unroll
        for (int off = 16; off; off >>= 1) {
            float ov = __shfl_down_sync(0xffffffffu, bvn, off);
            int   oj = __shfl_down_sync(0xffffffffu, bjn, off);
            if (ov > bvn || (ov == bvn && oj < bjn)) { bvn = ov; bjn = oj; }
        }
        bvn = __shfl_sync(0xffffffffu, bvn, 0);
        bjn = __shfl_sync(0xffffffffu, bjn, 0);

        float se2 = 0.0f;
#pragma unroll
        for (int k = 0; k < 32; k++) {
            int j = k * 32 + lane;
            if (j < NC) se2 += expf(u[k] - bvn);
        }
#pragma unroll
        for (int off = 16; off; off >>= 1) se2 += __shfl_xor_sync(0xffffffffu, se2, off);

        uyNew = __shfl_sync(0xffffffffu, uyNew, y & 31);

        lse = bvn + logf(se2);
        uy  = uyNew;

        if (t < 100) {
            if (lane == 0) sKey[w] = make_key(1.0f / se2, i, bjn);
            __syncthreads();
            if (tid == 0) {
                unsigned long long kk = sKey[0];
#pragma unroll
                for (int q = 1; q < 4; q++) if (sKey[q] > kk) kk = sKey[q];
                atomicMax(&g_key[t + 1].k, kk);
                red_release_add1(&g_cnt[t + 1].c);
            }
        }
    }

    // ---- final writeback ----
#pragma unroll
    for (int k = 0; k < 32; k++) {
        int j = k * 32 + lane;
        if (j < NC) Urow[j] = u[k];
    }
}

// =====================================================================
extern "C" void kernel_launch(void* const* d_in, const int* in_sizes, int n_in,
                              void* d_out, int out_size)
{
    const float* x = (const float*)d_in[0];
    const float* W = (const float*)d_in[1];
    const float* b = (const float*)d_in[2];
    float* U = (float*)d_out;

    // One-time: verify smem-m,v variant is fully co-resident (deadlock-proof).
    static int useSmem = -1;
    if (useSmem < 0) {
        cudaFuncSetAttribute(persist_steps<true>,
                             cudaFuncAttributePreferredSharedMemoryCarveout, 100);
        int occ = 0, sms = 0, dev = 0;
        cudaGetDevice(&dev);
        cudaDeviceGetAttribute(&sms, cudaDevAttrMultiProcessorCount, dev);
        cudaOccupancyMaxActiveBlocksPerMultiprocessor(
            &occ, persist_steps<true>, 128, 0);
        useSmem = (occ * sms >= NBLK) ? 1 : 0;
    }

    dim3 ggrid((NC + 63) / 64, NB / 64);      // (16, 64) = 1024 blocks
    sgemm_bias<<<ggrid, 256>>>(x, W, b, U);   // also zeroes barrier state

    if (useSmem) persist_steps<true><<<NBLK, 128>>>(U);
    else         persist_steps<false><<<NBLK, 128>>>(U);
}